// round 6
// baseline (speedup 1.0000x reference)
#include <cuda_runtime.h>

#define BATCH  2
#define NV     4096
#define NF     4096
#define IMG_H  256
#define IMG_W  256
#define CHUNK  128
#define NVERT  (3 * CHUNK)    // 384 vertex tasks per chunk
#define ROWS_PB 2             // rows per block
#define THREADS (IMG_W * ROWS_PB)   // 512

// ---------------------------------------------------------------------------
// Block = 2 image rows (512 px, 512 threads). Staging: threads 0..383 each
// transform exactly ONE vertex of the 128-triangle chunk into smem (chunk-0
// indices prefetched before VP setup so the global misses overlap). Pixel
// test evaluates triangles 4 at a time as a pure OR (value-identical to the
// sequential early-exit; coverage is order-independent), giving the LDS pipe
// 12 independent loads in flight. Expression order matches the reference
// (rel_err == 0).
// ---------------------------------------------------------------------------
__global__ void __launch_bounds__(THREADS) raster_block(
    const float* __restrict__ verts,   // [B,NV,3]
    const int*   __restrict__ faces,   // [B,NF,3]
    const float* __restrict__ Rm,      // [B,3,3]
    const float* __restrict__ Tm,      // [B,3]
    float*       __restrict__ out)     // [B,H,W,3]
{
    __shared__ float2 sxy[NVERT];      // transformed ndc (x,y) per corner

    int rowsPerBatch = IMG_H / ROWS_PB;           // 128 blocks per batch
    int b  = blockIdx.x / rowsPerBatch;
    int y0 = (blockIdx.x - b * rowsPerBatch) * ROWS_PB;
    int x  = threadIdx.x & (IMG_W - 1);
    int y  = y0 + (threadIdx.x >> 8);

    const int*   fb = faces + b * NF * 3;
    const float* vb = verts + b * NV * 3;

    // ---- prefetch chunk-0 face index (independent of R/T loads) ----
    bool stager = threadIdx.x < NVERT;
    int  pidx   = stager ? __ldg(&fb[threadIdx.x]) : 0;

    // pixel center in ndc (same expression order as reference)
    float px = (((float)x + 0.5f) / (float)IMG_W) * 2.0f - 1.0f;
    float py = (((float)y + 0.5f) / (float)IMG_H) * 2.0f - 1.0f;

    // ---- VP rows for this batch (uniform loads; identical ordering) ----
    const float* R = Rm + b * 9;
    const float* T = Tm + b * 3;

    float t0 = -((R[0] * T[0] + R[3] * T[1]) + R[6] * T[2]);
    float t1 = -((R[1] * T[0] + R[4] * T[1]) + R[7] * T[2]);
    float t2 = -((R[2] * T[0] + R[5] * T[1]) + R[8] * T[2]);

    const float f = 1.7320508075688772f;   // 1/tan(30 deg)

    float VP00 = f * R[0], VP01 = f * R[3], VP02 = f * R[6], VP03 = f * t0;
    float VP10 = f * R[1], VP11 = f * R[4], VP12 = f * R[7], VP13 = f * t1;
    float VP30 = -R[2],    VP31 = -R[5],    VP32 = -R[8],    VP33 = -t2;

    // one vertex task: gather + transform + smem store (2 divides)
    auto stage_vertex = [&](int v, int idx) {
        float a0 = __ldg(&vb[idx * 3 + 0]);
        float a1 = __ldg(&vb[idx * 3 + 1]);
        float a2 = __ldg(&vb[idx * 3 + 2]);
        float cx = ((a0 * VP00 + a1 * VP01) + a2 * VP02) + VP03;
        float cy = ((a0 * VP10 + a1 * VP11) + a2 * VP12) + VP13;
        float cw = ((a0 * VP30 + a1 * VP31) + a2 * VP32) + VP33;
        float w  = fmaxf(cw, 1e-8f);
        sxy[v] = make_float2(cx / w, cy / w);
    };

    // inside-test for one staged triangle (order matches reference)
    auto tri_inside = [&](int i) -> bool {
        float2 p0 = sxy[3 * i + 0];
        float2 p1 = sxy[3 * i + 1];
        float2 p2 = sxy[3 * i + 2];
        float e0 = (p1.x - p0.x) * (py - p0.y) - (p1.y - p0.y) * (px - p0.x);
        float e1 = (p2.x - p1.x) * (py - p1.y) - (p2.y - p1.y) * (px - p1.x);
        float e2 = (p0.x - p2.x) * (py - p2.y) - (p0.y - p2.y) * (px - p2.x);
        bool pos = (e0 >= 0.0f) & (e1 >= 0.0f) & (e2 >= 0.0f);
        bool neg = (e0 <= 0.0f) & (e1 <= 0.0f) & (e2 <= 0.0f);
        return pos | neg;
    };

    // test staged chunk, 4 triangles per iteration (OR is order-independent)
    auto test_chunk = [&](float covered) {
        if (covered == 0.0f) {
            for (int i = 0; i < CHUNK; i += 4) {
                bool hit = tri_inside(i)     | tri_inside(i + 1)
                         | tri_inside(i + 2) | tri_inside(i + 3);
                if (hit) { covered = 1.0f; break; }
            }
        }
        return covered;
    };

    float covered = 0.0f;

    // ---- chunk 0 (peeled; uses prefetched index) ----
    if (stager) stage_vertex(threadIdx.x, pidx);
    __syncthreads();

    covered = test_chunk(covered);

    if (!__syncthreads_and(covered != 0.0f)) {
        // ---- remaining chunks ----
        for (int ct = 1; ct < NF / CHUNK; ++ct) {
            const int* fc = fb + ct * NVERT;
            if (stager) {
                int idx = __ldg(&fc[threadIdx.x]);
                stage_vertex(threadIdx.x, idx);
            }
            __syncthreads();

            covered = test_chunk(covered);

            if (__syncthreads_and(covered != 0.0f)) break;
        }
    }

    int pix = (b * IMG_H + y) * IMG_W + x;
    float* o = out + (size_t)pix * 3;
    o[0] = covered;
    o[1] = covered;
    o[2] = covered;
}

// ---------------------------------------------------------------------------
extern "C" void kernel_launch(void* const* d_in, const int* in_sizes, int n_in,
                              void* d_out, int out_size) {
    const float* verts = (const float*)d_in[0];   // [2,4096,3]
    const int*   faces = (const int*)  d_in[1];   // [2,4096,3]
    const float* Rm    = (const float*)d_in[2];   // [2,3,3]
    const float* Tm    = (const float*)d_in[3];   // [2,3]
    float* out = (float*)d_out;                   // [2,256,256,3]

    raster_block<<<BATCH * (IMG_H / ROWS_PB), THREADS>>>(verts, faces, Rm, Tm, out);
}